// round 15
// baseline (speedup 1.0000x reference)
#include <cuda_runtime.h>
#include <cuda_bf16.h>
#include <cstdint>

#define BB   4
#define SS   2048
#define DM   1024
#define HH   16
#define DH   64
#define ROWS (BB*SS)          // 8192
#define OUTE  8388608LL
#define ATTNE 268435456LL

// ====================== PTX helpers (sm_80-compatible) ======================
__device__ __forceinline__ uint32_t smem_u32(const void* p) {
    uint32_t a;
    asm("{ .reg .u64 t; cvta.to.shared.u64 t, %1; cvt.u32.u64 %0, t; }"
        : "=r"(a) : "l"(p));
    return a;
}
__device__ __forceinline__ void ldm_x4(uint32_t& r0, uint32_t& r1, uint32_t& r2,
                                       uint32_t& r3, uint32_t a) {
    asm volatile("ldmatrix.sync.aligned.m8n8.x4.shared.b16 {%0,%1,%2,%3}, [%4];"
        : "=r"(r0), "=r"(r1), "=r"(r2), "=r"(r3) : "r"(a));
}
__device__ __forceinline__ void ldm_x2(uint32_t& r0, uint32_t& r1, uint32_t a) {
    asm volatile("ldmatrix.sync.aligned.m8n8.x2.shared.b16 {%0,%1}, [%2];"
        : "=r"(r0), "=r"(r1) : "r"(a));
}
__device__ __forceinline__ void ldm_x2t(uint32_t& r0, uint32_t& r1, uint32_t a) {
    asm volatile("ldmatrix.sync.aligned.m8n8.x2.trans.shared.b16 {%0,%1}, [%2];"
        : "=r"(r0), "=r"(r1) : "r"(a));
}
__device__ __forceinline__ void mma16816(float* c, const uint32_t* a, const uint32_t* b) {
    asm volatile("mma.sync.aligned.m16n8k16.row.col.f32.bf16.bf16.f32 "
        "{%0,%1,%2,%3}, {%4,%5,%6,%7}, {%8,%9}, {%0,%1,%2,%3};"
        : "+f"(c[0]), "+f"(c[1]), "+f"(c[2]), "+f"(c[3])
        : "r"(a[0]), "r"(a[1]), "r"(a[2]), "r"(a[3]), "r"(b[0]), "r"(b[1]));
}
__device__ __forceinline__ void cpa16(uint32_t s, const void* g) {
    asm volatile("cp.async.cg.shared.global [%0], [%1], 16;" :: "r"(s), "l"(g));
}
#define CP_COMMIT() asm volatile("cp.async.commit_group;" ::: "memory")
#define CP_WAIT(n)  asm volatile("cp.async.wait_group %0;" :: "n"(n) : "memory")

__device__ __forceinline__ void split2(float a, float b, uint32_t& hi, uint32_t& lo) {
    __nv_bfloat16 ha = __float2bfloat16(a), hb = __float2bfloat16(b);
    float ra = a - __bfloat162float(ha), rb = b - __bfloat162float(hb);
    __nv_bfloat162 H; H.x = ha; H.y = hb;
    __nv_bfloat162 L; L.x = __float2bfloat16(ra); L.y = __float2bfloat16(rb);
    hi = *reinterpret_cast<uint32_t*>(&H);
    lo = *reinterpret_cast<uint32_t*>(&L);
}

// ====================== device scratch ======================================
__device__ __nv_bfloat16 g_Ihi[3][ROWS*DM], g_Ilo[3][ROWS*DM];
__device__ __nv_bfloat16 g_Whi[4][DM*DM],   g_Wlo[4][DM*DM];   // W^T [n][k]
__device__ __nv_bfloat16 g_Qhi[ROWS*DM], g_Qlo[ROWS*DM];       // [bh][s][64]
__device__ __nv_bfloat16 g_Khi[ROWS*DM], g_Klo[ROWS*DM];
__device__ __nv_bfloat16 g_Vhi[ROWS*DM], g_Vlo[ROWS*DM];       // [bh][s][64]
__device__ __nv_bfloat16 g_Chi[ROWS*DM], g_Clo[ROWS*DM];       // ctx [b][s][1024]
__device__ float g_S[268435456];                               // fallback scores

// ====================== merged split kernels ================================
__global__ void __launch_bounds__(256) split_rm3(
    const float* __restrict__ X0, const float* __restrict__ X1,
    const float* __restrict__ X2, __nv_bfloat16* __restrict__ hi,
    __nv_bfloat16* __restrict__ lo, int n4)
{
    int i = blockIdx.x * 256 + threadIdx.x;
    if (i >= n4) return;
    const float* X = (blockIdx.y == 0) ? X0 : (blockIdx.y == 1) ? X1 : X2;
    size_t off = (size_t)blockIdx.y * (ROWS*DM/4);
    float4 v = ((const float4*)X)[i];
    uint32_t h0, l0, h1, l1;
    split2(v.x, v.y, h0, l0);
    split2(v.z, v.w, h1, l1);
    ((uint2*)hi)[off + i] = make_uint2(h0, h1);
    ((uint2*)lo)[off + i] = make_uint2(l0, l1);
}

// W[K][N] -> T[N][K] hi/lo, 4 weights in one launch (z selects)
__global__ void __launch_bounds__(256) split_w4(
    const float* __restrict__ W0, const float* __restrict__ W1,
    const float* __restrict__ W2, const float* __restrict__ W3,
    __nv_bfloat16* __restrict__ Thi, __nv_bfloat16* __restrict__ Tlo)
{
    __shared__ float ts[32][33];
    const float* W = (blockIdx.z == 0) ? W0 : (blockIdx.z == 1) ? W1
                   : (blockIdx.z == 2) ? W2 : W3;
    size_t zo = (size_t)blockIdx.z * DM * DM;
    int c0 = blockIdx.x * 32, r0 = blockIdx.y * 32;
    int tx = threadIdx.x & 31, ty = threadIdx.x >> 5;
    #pragma unroll
    for (int i = 0; i < 4; i++)
        ts[ty + i*8][tx] = W[(size_t)(r0 + ty + i*8) * DM + c0 + tx];
    __syncthreads();
    #pragma unroll
    for (int i = 0; i < 4; i++) {
        int nn = ty + i*8;
        float x = ts[tx][nn];
        __nv_bfloat16 h = __float2bfloat16(x);
        __nv_bfloat16 l = __float2bfloat16(x - __bfloat162float(h));
        size_t o = zo + (size_t)(c0 + nn) * DM + r0 + tx;
        Thi[o] = h; Tlo[o] = l;
    }
}

// ====================== projection GEMM (mma.sync) ==========================
__global__ void __launch_bounds__(256) gemm_proj_mma(
    const __nv_bfloat16* __restrict__ Ahi, const __nv_bfloat16* __restrict__ Alo,
    const __nv_bfloat16* __restrict__ Bhi, const __nv_bfloat16* __restrict__ Blo,
    const float* __restrict__ bias, float scale, int mode,
    float* __restrict__ outf, __nv_bfloat16* __restrict__ Ohi,
    __nv_bfloat16* __restrict__ Olo)
{
    extern __shared__ char sm[];
    const int tid = threadIdx.x, warp = tid >> 5, lane = tid & 31;
    const int m0 = blockIdx.y * 128, nb0 = blockIdx.x * 128;
    const int wm = (warp >> 2) * 64, wn = (warp & 3) * 32;
    const uint32_t smb = smem_u32(sm);

    float acc[4][4][4];
    #pragma unroll
    for (int i = 0; i < 4; i++)
        #pragma unroll
        for (int j = 0; j < 4; j++)
            #pragma unroll
            for (int q = 0; q < 4; q++) acc[i][j][q] = 0.f;

    const int lrow = tid >> 1, lk0 = (tid & 1) * 2;
    const size_t gA = (size_t)(m0 + lrow) * DM + lk0 * 8;
    const size_t gB = (size_t)(nb0 + lrow) * DM + lk0 * 8;
    const uint32_t sA0 = (uint32_t)(lrow*4 + ((lk0)   ^ (lrow & 3))) << 4;
    const uint32_t sA1 = (uint32_t)(lrow*4 + ((lk0+1) ^ (lrow & 3))) << 4;

#define PJ_PREFETCH(kc, st) do { \
    uint32_t b_ = smb + (st) * 32768; \
    const __nv_bfloat16* a0_ = Ahi + gA + (kc)*32; \
    const __nv_bfloat16* a1_ = Alo + gA + (kc)*32; \
    const __nv_bfloat16* b0_ = Bhi + gB + (kc)*32; \
    const __nv_bfloat16* b1_ = Blo + gB + (kc)*32; \
    cpa16(b_ + sA0, a0_);          cpa16(b_ + sA1, a0_ + 8); \
    cpa16(b_ + 8192  + sA0, a1_);  cpa16(b_ + 8192  + sA1, a1_ + 8); \
    cpa16(b_ + 16384 + sA0, b0_);  cpa16(b_ + 16384 + sA1, b0_ + 8); \
    cpa16(b_ + 24576 + sA0, b1_);  cpa16(b_ + 24576 + sA1, b1_ + 8); \
} while (0)

    PJ_PREFETCH(0, 0); CP_COMMIT();
    for (int kc = 0; kc < 32; kc++) {
        if (kc + 1 < 32) { PJ_PREFETCH(kc + 1, (kc + 1) & 1); CP_COMMIT(); CP_WAIT(1); }
        else CP_WAIT(0);
        __syncthreads();
        const uint32_t ab = smb + (kc & 1) * 32768;
        #pragma unroll
        for (int ks = 0; ks < 2; ks++) {
            uint32_t Ah[4][4], Al[4][4], Bh[4][2], Bl[4][2];
            #pragma unroll
            for (int mf = 0; mf < 4; mf++) {
                int r = wm + mf*16 + (lane & 15);
                int ku = ks*2 + (lane >> 4);
                uint32_t ad = ab + ((uint32_t)(r*4 + (ku ^ (r & 3))) << 4);
                ldm_x4(Ah[mf][0], Ah[mf][1], Ah[mf][2], Ah[mf][3], ad);
                ldm_x4(Al[mf][0], Al[mf][1], Al[mf][2], Al[mf][3], ad + 8192);
            }
            #pragma unroll
            for (int nf = 0; nf < 4; nf++) {
                int r = wn + nf*8 + (lane & 7);
                int ku = ks*2 + ((lane >> 3) & 1);
                uint32_t bd = ab + 16384 + ((uint32_t)(r*4 + (ku ^ (r & 3))) << 4);
                ldm_x2(Bh[nf][0], Bh[nf][1], bd);
                ldm_x2(Bl[nf][0], Bl[nf][1], bd + 8192);
            }
            #pragma unroll
            for (int mf = 0; mf < 4; mf++)
                #pragma unroll
                for (int nf = 0; nf < 4; nf++) {
                    mma16816(acc[mf][nf], Ah[mf], Bh[nf]);
                    mma16816(acc[mf][nf], Al[mf], Bh[nf]);
                    mma16816(acc[mf][nf], Ah[mf], Bl[nf]);
                }
        }
        __syncthreads();
    }
#undef PJ_PREFETCH

    float bnv[4][2];
    #pragma unroll
    for (int nf = 0; nf < 4; nf++) {
        int n = nb0 + wn + nf*8 + (lane & 3)*2;
        bnv[nf][0] = bias[n]; bnv[nf][1] = bias[n+1];
    }
    #pragma unroll
    for (int mf = 0; mf < 4; mf++)
        #pragma unroll
        for (int nf = 0; nf < 4; nf++) {
            int n = nb0 + wn + nf*8 + (lane & 3)*2;
            #pragma unroll
            for (int hf = 0; hf < 2; hf++) {
                int row = m0 + wm + mf*16 + (lane >> 2) + hf*8;
                float v0 = (acc[mf][nf][hf*2+0] + bnv[nf][0]) * scale;
                float v1 = (acc[mf][nf][hf*2+1] + bnv[nf][1]) * scale;
                if (mode == 0) {
                    int b = row >> 11, s = row & 2047, h = n >> 6, d = n & 63;
                    size_t o = (((size_t)(b*16 + h))*2048 + s)*64 + d;
                    uint32_t H, L; split2(v0, v1, H, L);
                    *(uint32_t*)(Ohi + o) = H;
                    *(uint32_t*)(Olo + o) = L;
                } else {
                    *(float2*)(outf + (size_t)row*DM + n) = make_float2(v0, v1);
                }
            }
        }
}

// ====================== scores GEMM =========================================
__global__ void __launch_bounds__(256) gemm_scores_mma(
    const __nv_bfloat16* __restrict__ Qhi, const __nv_bfloat16* __restrict__ Qlo,
    const __nv_bfloat16* __restrict__ Khi, const __nv_bfloat16* __restrict__ Klo,
    float* __restrict__ S)
{
    extern __shared__ char sm[];
    const int tid = threadIdx.x, warp = tid >> 5, lane = tid & 31;
    const int n0 = blockIdx.x * 128, m0 = blockIdx.y * 128;
    const size_t bh = blockIdx.z;
    const int wm = (warp >> 2) * 64, wn = (warp & 3) * 32;
    const uint32_t smb = smem_u32(sm);

    const int lrow = tid >> 1, lk0 = (tid & 1) * 4;
    const __nv_bfloat16* Qh = Qhi + (bh*2048 + m0 + lrow)*64 + lk0*8;
    const __nv_bfloat16* Ql = Qlo + (bh*2048 + m0 + lrow)*64 + lk0*8;
    const __nv_bfloat16* Kh = Khi + (bh*2048 + n0 + lrow)*64 + lk0*8;
    const __nv_bfloat16* Kl = Klo + (bh*2048 + n0 + lrow)*64 + lk0*8;
    #pragma unroll
    for (int u = 0; u < 4; u++) {
        uint32_t so = (uint32_t)(lrow*8 + ((lk0 + u) ^ (lrow & 7))) << 4;
        cpa16(smb + so,          Qh + u*8);
        cpa16(smb + 16384 + so,  Ql + u*8);
        cpa16(smb + 32768 + so,  Kh + u*8);
        cpa16(smb + 49152 + so,  Kl + u*8);
    }
    CP_COMMIT(); CP_WAIT(0);
    __syncthreads();

    float acc[4][4][4];
    #pragma unroll
    for (int i = 0; i < 4; i++)
        #pragma unroll
        for (int j = 0; j < 4; j++)
            #pragma unroll
            for (int q = 0; q < 4; q++) acc[i][j][q] = 0.f;

    #pragma unroll
    for (int ks = 0; ks < 4; ks++) {
        uint32_t Ah[4][4], Al[4][4], Bh[4][2], Bl[4][2];
        #pragma unroll
        for (int mf = 0; mf < 4; mf++) {
            int r = wm + mf*16 + (lane & 15);
            int ku = ks*2 + (lane >> 4);
            uint32_t ad = smb + ((uint32_t)(r*8 + (ku ^ (r & 7))) << 4);
            ldm_x4(Ah[mf][0], Ah[mf][1], Ah[mf][2], Ah[mf][3], ad);
            ldm_x4(Al[mf][0], Al[mf][1], Al[mf][2], Al[mf][3], ad + 16384);
        }
        #pragma unroll
        for (int nf = 0; nf < 4; nf++) {
            int r = wn + nf*8 + (lane & 7);
            int ku = ks*2 + ((lane >> 3) & 1);
            uint32_t bd = smb + 32768 + ((uint32_t)(r*8 + (ku ^ (r & 7))) << 4);
            ldm_x2(Bh[nf][0], Bh[nf][1], bd);
            ldm_x2(Bl[nf][0], Bl[nf][1], bd + 16384);
        }
        #pragma unroll
        for (int mf = 0; mf < 4; mf++)
            #pragma unroll
            for (int nf = 0; nf < 4; nf++) {
                mma16816(acc[mf][nf], Ah[mf], Bh[nf]);
                mma16816(acc[mf][nf], Al[mf], Bh[nf]);
                mma16816(acc[mf][nf], Ah[mf], Bl[nf]);
            }
    }

    float* Sb = S + (bh*2048 + (size_t)m0)*2048 + n0;
    #pragma unroll
    for (int mf = 0; mf < 4; mf++)
        #pragma unroll
        for (int nf = 0; nf < 4; nf++) {
            int n = wn + nf*8 + (lane & 3)*2;
            #pragma unroll
            for (int hf = 0; hf < 2; hf++) {
                int m = wm + mf*16 + (lane >> 2) + hf*8;
                *(float2*)(Sb + (size_t)m*2048 + n) =
                    make_float2(acc[mf][nf][hf*2+0], acc[mf][nf][hf*2+1]);
            }
        }
}

// ====================== softmax (in place, warp per row) ====================
__global__ void __launch_bounds__(256) softmax_k(float* __restrict__ S)
{
    size_t rowi = (size_t)blockIdx.x * 8 + (threadIdx.x >> 5);
    int lane = threadIdx.x & 31;
    float4* row = (float4*)(S + rowi * 2048);
    float4 f[16];
    #pragma unroll
    for (int i = 0; i < 16; i++) f[i] = row[i*32 + lane];
    float m = -3.4e38f;
    #pragma unroll
    for (int i = 0; i < 16; i++)
        m = fmaxf(m, fmaxf(fmaxf(f[i].x, f[i].y), fmaxf(f[i].z, f[i].w)));
    #pragma unroll
    for (int o = 16; o; o >>= 1) m = fmaxf(m, __shfl_xor_sync(0xffffffffu, m, o));
    float sum = 0.f;
    #pragma unroll
    for (int i = 0; i < 16; i++) {
        f[i].x = __expf(f[i].x - m); f[i].y = __expf(f[i].y - m);
        f[i].z = __expf(f[i].z - m); f[i].w = __expf(f[i].w - m);
        sum += f[i].x + f[i].y + f[i].z + f[i].w;
    }
    #pragma unroll
    for (int o = 16; o; o >>= 1) sum += __shfl_xor_sync(0xffffffffu, sum, o);
    float inv = 1.f / sum;
    #pragma unroll
    for (int i = 0; i < 16; i++) {
        f[i].x *= inv; f[i].y *= inv; f[i].z *= inv; f[i].w *= inv;
        row[i*32 + lane] = f[i];
    }
}

// ====================== PV GEMM (reads normalized fp32 S) ===================
// ctx[bh][m0..+128][64] = P @ V. A double-buffered (split-only conversion),
// V double-buffered via cp.async issued AFTER the barrier (WAR-safe).
// smem: A stages [0,64K) (each 32K: hi 16K + lo 16K), V stages [64K,96K).
__global__ void __launch_bounds__(256) gemm_pv_fused(
    const float* __restrict__ S,
    const __nv_bfloat16* __restrict__ Vhi, const __nv_bfloat16* __restrict__ Vlo,
    __nv_bfloat16* __restrict__ Chi, __nv_bfloat16* __restrict__ Clo)
{
    extern __shared__ char sm[];
    const int tid = threadIdx.x, warp = tid >> 5, lane = tid & 31;
    const int m0 = blockIdx.x * 128;
    const size_t bh = blockIdx.y;
    const int b = (int)(bh >> 4), h = (int)(bh & 15);
    const int wm = (warp & 3) * 32, wn = (warp >> 2) * 32;
    const uint32_t smb = smem_u32(sm);

    float acc[2][4][4];
    #pragma unroll
    for (int i = 0; i < 2; i++)
        #pragma unroll
        for (int j = 0; j < 4; j++)
            #pragma unroll
            for (int q = 0; q < 4; q++) acc[i][j][q] = 0.f;

    // coalesced S-chunk mapping: thread covers rows u*16+(tid>>4), cols (tid&15)*4
    const int frow = tid >> 4, fcol = (tid & 15) * 4;
    const float* Sbase = S + (bh*2048 + (size_t)m0 + frow)*2048 + fcol;
    const int k8 = (tid & 15) >> 1, lo8 = (tid & 1) * 8;

    const int vrow = tid >> 2, vk0 = (tid & 3) * 2;

#define PVF_V(kc, stg) do { \
    uint32_t b_ = smb + 65536 + (stg) * 16384; \
    size_t gv_ = (bh*2048 + (size_t)(kc)*64 + vrow)*64 + vk0*8; \
    _Pragma("unroll") \
    for (int u = 0; u < 2; u++) { \
        uint32_t so = (uint32_t)(vrow*8 + ((vk0 + u) ^ (vrow & 7))) << 4; \
        cpa16(b_ + so,        Vhi + gv_ + u*8); \
        cpa16(b_ + 8192 + so, Vlo + gv_ + u*8); \
    } \
} while (0)

#define PVF_CONV(F, stg) do { \
    char* ab_ = sm + (stg) * 32768; \
    _Pragma("unroll") \
    for (int u = 0; u < 8; u++) { \
        int r_ = u*16 + frow; \
        uint32_t h0, l0, h1, l1; \
        split2((F)[u].x, (F)[u].y, h0, l0); \
        split2((F)[u].z, (F)[u].w, h1, l1); \
        uint32_t so = (uint32_t)(r_*128 + ((k8 ^ (r_ & 7)) << 4) + lo8); \
        *(uint2*)(ab_ + so)         = make_uint2(h0, h1); \
        *(uint2*)(ab_ + 16384 + so) = make_uint2(l0, l1); \
    } \
} while (0)

    // prologue: chunk 0 regs -> A stage 0; V stage 0 in flight
    float4 F[8];
    #pragma unroll
    for (int u = 0; u < 8; u++) F[u] = *(const float4*)(Sbase + (size_t)u*16*2048);
    PVF_CONV(F, 0);
    PVF_V(0, 0); CP_COMMIT();

    for (int kc = 0; kc < 32; kc++) {
        CP_WAIT(0);               // V(kc) landed (only group in flight)
        __syncthreads();          // A(kc) conv-writes visible; all prior-stage reads done
        if (kc + 1 < 32) {
            PVF_V(kc + 1, (kc + 1) & 1); CP_COMMIT();   // WAR-safe: after barrier
            #pragma unroll
            for (int u = 0; u < 8; u++)
                F[u] = *(const float4*)(Sbase + (size_t)u*16*2048 + (kc+1)*64);
        }
        const uint32_t ab = smb + (kc & 1) * 32768;
        const uint32_t vb = smb + 65536 + (kc & 1) * 16384;
        #pragma unroll
        for (int ks = 0; ks < 4; ks++) {
            uint32_t Ah[2][4], Al[2][4], Bh[4][2], Bl[4][2];
            #pragma unroll
            for (int mf = 0; mf < 2; mf++) {
                int r = wm + mf*16 + (lane & 15);
                int ku = ks*2 + (lane >> 4);
                uint32_t ad = ab + ((uint32_t)(r*8 + (ku ^ (r & 7))) << 4);
                ldm_x4(Ah[mf][0], Ah[mf][1], Ah[mf][2], Ah[mf][3], ad);
                ldm_x4(Al[mf][0], Al[mf][1], Al[mf][2], Al[mf][3], ad + 16384);
            }
            #pragma unroll
            for (int nf = 0; nf < 4; nf++) {
                int r = ks*16 + (lane & 15);
                int nu = (wn >> 3) + nf;
                uint32_t bd = vb + ((uint32_t)(r*8 + (nu ^ (r & 7))) << 4);
                ldm_x2t(Bh[nf][0], Bh[nf][1], bd);
                ldm_x2t(Bl[nf][0], Bl[nf][1], bd + 8192);
            }
            #pragma unroll
            for (int mf = 0; mf < 2; mf++)
                #pragma unroll
                for (int nf = 0; nf < 4; nf++) {
                    mma16816(acc[mf][nf], Ah[mf], Bh[nf]);
                    mma16816(acc[mf][nf], Al[mf], Bh[nf]);
                    mma16816(acc[mf][nf], Ah[mf], Bl[nf]);
                }
        }
        // convert next chunk into the other A stage (read at next barrier)
        if (kc + 1 < 32) PVF_CONV(F, (kc + 1) & 1);
    }
#undef PVF_V
#undef PVF_CONV

    #pragma unroll
    for (int mf = 0; mf < 2; mf++)
        #pragma unroll
        for (int nf = 0; nf < 4; nf++) {
            int n = wn + nf*8 + (lane & 3)*2;     // d
            #pragma unroll
            for (int hf = 0; hf < 2; hf++) {
                int m = wm + mf*16 + (lane >> 2) + hf*8;
                size_t o = ((size_t)b*2048 + m0 + m)*1024 + h*64 + n;
                uint32_t H, L;
                split2(acc[mf][nf][hf*2+0], acc[mf][nf][hf*2+1], H, L);
                *(uint32_t*)(Chi + o) = H;
                *(uint32_t*)(Clo + o) = L;
            }
        }
}

// ====================== host ================================================
extern "C" void kernel_launch(void* const* d_in, const int* in_sizes, int n_in,
                              void* d_out, int out_size)
{
    const float* q  = (const float*)d_in[0];
    const float* k  = (const float*)d_in[1];
    const float* v  = (const float*)d_in[2];
    const float* Wq = (const float*)d_in[3];
    const float* bq = (const float*)d_in[4];
    const float* Wk = (const float*)d_in[5];
    const float* bk = (const float*)d_in[6];
    const float* Wv = (const float*)d_in[7];
    const float* bv = (const float*)d_in[8];
    const float* Wo = (const float*)d_in[9];
    const float* bo = (const float*)d_in[10];

    float* outp = (float*)d_out;
    float* final_dst = nullptr;
    float* attn_dst  = nullptr;
    long long osz = (long long)out_size;
    if (osz >= OUTE + ATTNE)      { final_dst = outp; attn_dst = outp + OUTE; }
    else if (osz == ATTNE)        { attn_dst = outp; }
    else                          { final_dst = outp; }

    __nv_bfloat16 *pIhi, *pIlo, *pWhi, *pWlo, *pQhi, *pQlo, *pKhi, *pKlo;
    __nv_bfloat16 *pVhi, *pVlo, *pChi, *pClo;
    float* pS;
    cudaGetSymbolAddress((void**)&pIhi, g_Ihi);
    cudaGetSymbolAddress((void**)&pIlo, g_Ilo);
    cudaGetSymbolAddress((void**)&pWhi, g_Whi);
    cudaGetSymbolAddress((void**)&pWlo, g_Wlo);
    cudaGetSymbolAddress((void**)&pQhi, g_Qhi);
    cudaGetSymbolAddress((void**)&pQlo, g_Qlo);
    cudaGetSymbolAddress((void**)&pKhi, g_Khi);
    cudaGetSymbolAddress((void**)&pKlo, g_Klo);
    cudaGetSymbolAddress((void**)&pVhi, g_Vhi);
    cudaGetSymbolAddress((void**)&pVlo, g_Vlo);
    cudaGetSymbolAddress((void**)&pChi, g_Chi);
    cudaGetSymbolAddress((void**)&pClo, g_Clo);
    cudaGetSymbolAddress((void**)&pS,   g_S);

    float* Sbuf = attn_dst ? attn_dst : pS;

    cudaFuncSetAttribute(gemm_proj_mma,   cudaFuncAttributeMaxDynamicSharedMemorySize, 65536);
    cudaFuncSetAttribute(gemm_scores_mma, cudaFuncAttributeMaxDynamicSharedMemorySize, 65536);
    cudaFuncSetAttribute(gemm_pv_fused,   cudaFuncAttributeMaxDynamicSharedMemorySize, 98304);

    const int n4 = ROWS*DM/4;
    dim3 gr(n4/256, 3);
    split_rm3<<<gr, 256>>>(q, k, v, pIhi, pIlo, n4);
    dim3 gw(32, 32, 4);
    split_w4<<<gw, 256>>>(Wq, Wk, Wv, Wo, pWhi, pWlo);

    dim3 gp(8, 64);
    gemm_proj_mma<<<gp, 256, 65536>>>(pIhi, pIlo, pWhi, pWlo,
                                      bq, 0.125f, 0, nullptr, pQhi, pQlo);
    gemm_proj_mma<<<gp, 256, 65536>>>(pIhi + (size_t)ROWS*DM, pIlo + (size_t)ROWS*DM,
                                      pWhi + (size_t)DM*DM, pWlo + (size_t)DM*DM,
                                      bk, 1.0f, 0, nullptr, pKhi, pKlo);
    gemm_proj_mma<<<gp, 256, 65536>>>(pIhi + 2*(size_t)ROWS*DM, pIlo + 2*(size_t)ROWS*DM,
                                      pWhi + 2*(size_t)DM*DM, pWlo + 2*(size_t)DM*DM,
                                      bv, 1.0f, 0, nullptr, pVhi, pVlo);

    dim3 gs(16, 16, 64);
    gemm_scores_mma<<<gs, 256, 65536>>>(pQhi, pQlo, pKhi, pKlo, Sbuf);
    softmax_k<<<16384, 256>>>(Sbuf);

    if (final_dst) {
        dim3 gv(16, 64);
        gemm_pv_fused<<<gv, 256, 98304>>>(Sbuf, pVhi, pVlo, pChi, pClo);
        gemm_proj_mma<<<gp, 256, 65536>>>(pChi, pClo,
                                          pWhi + 3*(size_t)DM*DM, pWlo + 3*(size_t)DM*DM,
                                          bo, 1.0f, 1, final_dst, nullptr, nullptr);
    }
}

// round 16
// speedup vs baseline: 1.0012x; 1.0012x over previous
#include <cuda_runtime.h>
#include <cuda_bf16.h>
#include <cstdint>

#define BB   4
#define SS   2048
#define DM   1024
#define HH   16
#define DH   64
#define ROWS (BB*SS)          // 8192
#define OUTE  8388608LL
#define ATTNE 268435456LL

// ====================== PTX helpers (sm_80-compatible) ======================
__device__ __forceinline__ uint32_t smem_u32(const void* p) {
    uint32_t a;
    asm("{ .reg .u64 t; cvta.to.shared.u64 t, %1; cvt.u32.u64 %0, t; }"
        : "=r"(a) : "l"(p));
    return a;
}
__device__ __forceinline__ void ldm_x4(uint32_t& r0, uint32_t& r1, uint32_t& r2,
                                       uint32_t& r3, uint32_t a) {
    asm volatile("ldmatrix.sync.aligned.m8n8.x4.shared.b16 {%0,%1,%2,%3}, [%4];"
        : "=r"(r0), "=r"(r1), "=r"(r2), "=r"(r3) : "r"(a));
}
__device__ __forceinline__ void ldm_x2(uint32_t& r0, uint32_t& r1, uint32_t a) {
    asm volatile("ldmatrix.sync.aligned.m8n8.x2.shared.b16 {%0,%1}, [%2];"
        : "=r"(r0), "=r"(r1) : "r"(a));
}
__device__ __forceinline__ void ldm_x2t(uint32_t& r0, uint32_t& r1, uint32_t a) {
    asm volatile("ldmatrix.sync.aligned.m8n8.x2.trans.shared.b16 {%0,%1}, [%2];"
        : "=r"(r0), "=r"(r1) : "r"(a));
}
__device__ __forceinline__ void mma16816(float* c, const uint32_t* a, const uint32_t* b) {
    asm volatile("mma.sync.aligned.m16n8k16.row.col.f32.bf16.bf16.f32 "
        "{%0,%1,%2,%3}, {%4,%5,%6,%7}, {%8,%9}, {%0,%1,%2,%3};"
        : "+f"(c[0]), "+f"(c[1]), "+f"(c[2]), "+f"(c[3])
        : "r"(a[0]), "r"(a[1]), "r"(a[2]), "r"(a[3]), "r"(b[0]), "r"(b[1]));
}
__device__ __forceinline__ void cpa16(uint32_t s, const void* g) {
    asm volatile("cp.async.cg.shared.global [%0], [%1], 16;" :: "r"(s), "l"(g));
}
#define CP_COMMIT() asm volatile("cp.async.commit_group;" ::: "memory")
#define CP_WAIT(n)  asm volatile("cp.async.wait_group %0;" :: "n"(n) : "memory")

__device__ __forceinline__ void split2(float a, float b, uint32_t& hi, uint32_t& lo) {
    __nv_bfloat16 ha = __float2bfloat16(a), hb = __float2bfloat16(b);
    float ra = a - __bfloat162float(ha), rb = b - __bfloat162float(hb);
    __nv_bfloat162 H; H.x = ha; H.y = hb;
    __nv_bfloat162 L; L.x = __float2bfloat16(ra); L.y = __float2bfloat16(rb);
    hi = *reinterpret_cast<uint32_t*>(&H);
    lo = *reinterpret_cast<uint32_t*>(&L);
}

// ====================== device scratch ======================================
__device__ __nv_bfloat16 g_Ihi[3][ROWS*DM], g_Ilo[3][ROWS*DM];
__device__ __nv_bfloat16 g_Whi[4][DM*DM],   g_Wlo[4][DM*DM];   // W^T [n][k]
__device__ __nv_bfloat16 g_Qhi[ROWS*DM], g_Qlo[ROWS*DM];       // [bh][s][64]
__device__ __nv_bfloat16 g_Khi[ROWS*DM], g_Klo[ROWS*DM];
__device__ __nv_bfloat16 g_Vhi[ROWS*DM], g_Vlo[ROWS*DM];       // [bh][s][64]
__device__ __nv_bfloat16 g_Chi[ROWS*DM], g_Clo[ROWS*DM];       // ctx [b][s][1024]
__device__ float g_S[268435456];                               // fallback scores

// ====================== merged split kernels ================================
__global__ void __launch_bounds__(256) split_rm3(
    const float* __restrict__ X0, const float* __restrict__ X1,
    const float* __restrict__ X2, __nv_bfloat16* __restrict__ hi,
    __nv_bfloat16* __restrict__ lo, int n4)
{
    int i = blockIdx.x * 256 + threadIdx.x;
    if (i >= n4) return;
    const float* X = (blockIdx.y == 0) ? X0 : (blockIdx.y == 1) ? X1 : X2;
    size_t off = (size_t)blockIdx.y * (ROWS*DM/4);
    float4 v = ((const float4*)X)[i];
    uint32_t h0, l0, h1, l1;
    split2(v.x, v.y, h0, l0);
    split2(v.z, v.w, h1, l1);
    ((uint2*)hi)[off + i] = make_uint2(h0, h1);
    ((uint2*)lo)[off + i] = make_uint2(l0, l1);
}

// W[K][N] -> T[N][K] hi/lo, 4 weights in one launch (z selects)
__global__ void __launch_bounds__(256) split_w4(
    const float* __restrict__ W0, const float* __restrict__ W1,
    const float* __restrict__ W2, const float* __restrict__ W3,
    __nv_bfloat16* __restrict__ Thi, __nv_bfloat16* __restrict__ Tlo)
{
    __shared__ float ts[32][33];
    const float* W = (blockIdx.z == 0) ? W0 : (blockIdx.z == 1) ? W1
                   : (blockIdx.z == 2) ? W2 : W3;
    size_t zo = (size_t)blockIdx.z * DM * DM;
    int c0 = blockIdx.x * 32, r0 = blockIdx.y * 32;
    int tx = threadIdx.x & 31, ty = threadIdx.x >> 5;
    #pragma unroll
    for (int i = 0; i < 4; i++)
        ts[ty + i*8][tx] = W[(size_t)(r0 + ty + i*8) * DM + c0 + tx];
    __syncthreads();
    #pragma unroll
    for (int i = 0; i < 4; i++) {
        int nn = ty + i*8;
        float x = ts[tx][nn];
        __nv_bfloat16 h = __float2bfloat16(x);
        __nv_bfloat16 l = __float2bfloat16(x - __bfloat162float(h));
        size_t o = zo + (size_t)(c0 + nn) * DM + r0 + tx;
        Thi[o] = h; Tlo[o] = l;
    }
}

// ====================== projection GEMM (mma.sync) ==========================
__global__ void __launch_bounds__(256) gemm_proj_mma(
    const __nv_bfloat16* __restrict__ Ahi, const __nv_bfloat16* __restrict__ Alo,
    const __nv_bfloat16* __restrict__ Bhi, const __nv_bfloat16* __restrict__ Blo,
    const float* __restrict__ bias, float scale, int mode,
    float* __restrict__ outf, __nv_bfloat16* __restrict__ Ohi,
    __nv_bfloat16* __restrict__ Olo)
{
    extern __shared__ char sm[];
    const int tid = threadIdx.x, warp = tid >> 5, lane = tid & 31;
    const int m0 = blockIdx.y * 128, nb0 = blockIdx.x * 128;
    const int wm = (warp >> 2) * 64, wn = (warp & 3) * 32;
    const uint32_t smb = smem_u32(sm);

    float acc[4][4][4];
    #pragma unroll
    for (int i = 0; i < 4; i++)
        #pragma unroll
        for (int j = 0; j < 4; j++)
            #pragma unroll
            for (int q = 0; q < 4; q++) acc[i][j][q] = 0.f;

    const int lrow = tid >> 1, lk0 = (tid & 1) * 2;
    const size_t gA = (size_t)(m0 + lrow) * DM + lk0 * 8;
    const size_t gB = (size_t)(nb0 + lrow) * DM + lk0 * 8;
    const uint32_t sA0 = (uint32_t)(lrow*4 + ((lk0)   ^ (lrow & 3))) << 4;
    const uint32_t sA1 = (uint32_t)(lrow*4 + ((lk0+1) ^ (lrow & 3))) << 4;

#define PJ_PREFETCH(kc, st) do { \
    uint32_t b_ = smb + (st) * 32768; \
    const __nv_bfloat16* a0_ = Ahi + gA + (kc)*32; \
    const __nv_bfloat16* a1_ = Alo + gA + (kc)*32; \
    const __nv_bfloat16* b0_ = Bhi + gB + (kc)*32; \
    const __nv_bfloat16* b1_ = Blo + gB + (kc)*32; \
    cpa16(b_ + sA0, a0_);          cpa16(b_ + sA1, a0_ + 8); \
    cpa16(b_ + 8192  + sA0, a1_);  cpa16(b_ + 8192  + sA1, a1_ + 8); \
    cpa16(b_ + 16384 + sA0, b0_);  cpa16(b_ + 16384 + sA1, b0_ + 8); \
    cpa16(b_ + 24576 + sA0, b1_);  cpa16(b_ + 24576 + sA1, b1_ + 8); \
} while (0)

    PJ_PREFETCH(0, 0); CP_COMMIT();
    for (int kc = 0; kc < 32; kc++) {
        if (kc + 1 < 32) { PJ_PREFETCH(kc + 1, (kc + 1) & 1); CP_COMMIT(); CP_WAIT(1); }
        else CP_WAIT(0);
        __syncthreads();
        const uint32_t ab = smb + (kc & 1) * 32768;
        #pragma unroll
        for (int ks = 0; ks < 2; ks++) {
            uint32_t Ah[4][4], Al[4][4], Bh[4][2], Bl[4][2];
            #pragma unroll
            for (int mf = 0; mf < 4; mf++) {
                int r = wm + mf*16 + (lane & 15);
                int ku = ks*2 + (lane >> 4);
                uint32_t ad = ab + ((uint32_t)(r*4 + (ku ^ (r & 3))) << 4);
                ldm_x4(Ah[mf][0], Ah[mf][1], Ah[mf][2], Ah[mf][3], ad);
                ldm_x4(Al[mf][0], Al[mf][1], Al[mf][2], Al[mf][3], ad + 8192);
            }
            #pragma unroll
            for (int nf = 0; nf < 4; nf++) {
                int r = wn + nf*8 + (lane & 7);
                int ku = ks*2 + ((lane >> 3) & 1);
                uint32_t bd = ab + 16384 + ((uint32_t)(r*4 + (ku ^ (r & 3))) << 4);
                ldm_x2(Bh[nf][0], Bh[nf][1], bd);
                ldm_x2(Bl[nf][0], Bl[nf][1], bd + 8192);
            }
            #pragma unroll
            for (int mf = 0; mf < 4; mf++)
                #pragma unroll
                for (int nf = 0; nf < 4; nf++) {
                    mma16816(acc[mf][nf], Ah[mf], Bh[nf]);
                    mma16816(acc[mf][nf], Al[mf], Bh[nf]);
                    mma16816(acc[mf][nf], Ah[mf], Bl[nf]);
                }
        }
        __syncthreads();
    }
#undef PJ_PREFETCH

    float bnv[4][2];
    #pragma unroll
    for (int nf = 0; nf < 4; nf++) {
        int n = nb0 + wn + nf*8 + (lane & 3)*2;
        bnv[nf][0] = bias[n]; bnv[nf][1] = bias[n+1];
    }
    #pragma unroll
    for (int mf = 0; mf < 4; mf++)
        #pragma unroll
        for (int nf = 0; nf < 4; nf++) {
            int n = nb0 + wn + nf*8 + (lane & 3)*2;
            #pragma unroll
            for (int hf = 0; hf < 2; hf++) {
                int row = m0 + wm + mf*16 + (lane >> 2) + hf*8;
                float v0 = (acc[mf][nf][hf*2+0] + bnv[nf][0]) * scale;
                float v1 = (acc[mf][nf][hf*2+1] + bnv[nf][1]) * scale;
                if (mode == 0) {
                    int b = row >> 11, s = row & 2047, h = n >> 6, d = n & 63;
                    size_t o = (((size_t)(b*16 + h))*2048 + s)*64 + d;
                    uint32_t H, L; split2(v0, v1, H, L);
                    *(uint32_t*)(Ohi + o) = H;
                    *(uint32_t*)(Olo + o) = L;
                } else {
                    *(float2*)(outf + (size_t)row*DM + n) = make_float2(v0, v1);
                }
            }
        }
}

// ====================== scores GEMM =========================================
__global__ void __launch_bounds__(256) gemm_scores_mma(
    const __nv_bfloat16* __restrict__ Qhi, const __nv_bfloat16* __restrict__ Qlo,
    const __nv_bfloat16* __restrict__ Khi, const __nv_bfloat16* __restrict__ Klo,
    float* __restrict__ S)
{
    extern __shared__ char sm[];
    const int tid = threadIdx.x, warp = tid >> 5, lane = tid & 31;
    const int n0 = blockIdx.x * 128, m0 = blockIdx.y * 128;
    const size_t bh = blockIdx.z;
    const int wm = (warp >> 2) * 64, wn = (warp & 3) * 32;
    const uint32_t smb = smem_u32(sm);

    const int lrow = tid >> 1, lk0 = (tid & 1) * 4;
    const __nv_bfloat16* Qh = Qhi + (bh*2048 + m0 + lrow)*64 + lk0*8;
    const __nv_bfloat16* Ql = Qlo + (bh*2048 + m0 + lrow)*64 + lk0*8;
    const __nv_bfloat16* Kh = Khi + (bh*2048 + n0 + lrow)*64 + lk0*8;
    const __nv_bfloat16* Kl = Klo + (bh*2048 + n0 + lrow)*64 + lk0*8;
    #pragma unroll
    for (int u = 0; u < 4; u++) {
        uint32_t so = (uint32_t)(lrow*8 + ((lk0 + u) ^ (lrow & 7))) << 4;
        cpa16(smb + so,          Qh + u*8);
        cpa16(smb + 16384 + so,  Ql + u*8);
        cpa16(smb + 32768 + so,  Kh + u*8);
        cpa16(smb + 49152 + so,  Kl + u*8);
    }
    CP_COMMIT(); CP_WAIT(0);
    __syncthreads();

    float acc[4][4][4];
    #pragma unroll
    for (int i = 0; i < 4; i++)
        #pragma unroll
        for (int j = 0; j < 4; j++)
            #pragma unroll
            for (int q = 0; q < 4; q++) acc[i][j][q] = 0.f;

    #pragma unroll
    for (int ks = 0; ks < 4; ks++) {
        uint32_t Ah[4][4], Al[4][4], Bh[4][2], Bl[4][2];
        #pragma unroll
        for (int mf = 0; mf < 4; mf++) {
            int r = wm + mf*16 + (lane & 15);
            int ku = ks*2 + (lane >> 4);
            uint32_t ad = smb + ((uint32_t)(r*8 + (ku ^ (r & 7))) << 4);
            ldm_x4(Ah[mf][0], Ah[mf][1], Ah[mf][2], Ah[mf][3], ad);
            ldm_x4(Al[mf][0], Al[mf][1], Al[mf][2], Al[mf][3], ad + 16384);
        }
        #pragma unroll
        for (int nf = 0; nf < 4; nf++) {
            int r = wn + nf*8 + (lane & 7);
            int ku = ks*2 + ((lane >> 3) & 1);
            uint32_t bd = smb + 32768 + ((uint32_t)(r*8 + (ku ^ (r & 7))) << 4);
            ldm_x2(Bh[nf][0], Bh[nf][1], bd);
            ldm_x2(Bl[nf][0], Bl[nf][1], bd + 16384);
        }
        #pragma unroll
        for (int mf = 0; mf < 4; mf++)
            #pragma unroll
            for (int nf = 0; nf < 4; nf++) {
                mma16816(acc[mf][nf], Ah[mf], Bh[nf]);
                mma16816(acc[mf][nf], Al[mf], Bh[nf]);
                mma16816(acc[mf][nf], Ah[mf], Bl[nf]);
            }
    }

    float* Sb = S + (bh*2048 + (size_t)m0)*2048 + n0;
    #pragma unroll
    for (int mf = 0; mf < 4; mf++)
        #pragma unroll
        for (int nf = 0; nf < 4; nf++) {
            int n = wn + nf*8 + (lane & 3)*2;
            #pragma unroll
            for (int hf = 0; hf < 2; hf++) {
                int m = wm + mf*16 + (lane >> 2) + hf*8;
                *(float2*)(Sb + (size_t)m*2048 + n) =
                    make_float2(acc[mf][nf][hf*2+0], acc[mf][nf][hf*2+1]);
            }
        }
}

// ====================== softmax (in place, warp per row) ====================
__global__ void __launch_bounds__(256) softmax_k(float* __restrict__ S)
{
    size_t rowi = (size_t)blockIdx.x * 8 + (threadIdx.x >> 5);
    int lane = threadIdx.x & 31;
    float4* row = (float4*)(S + rowi * 2048);
    float4 f[16];
    #pragma unroll
    for (int i = 0; i < 16; i++) f[i] = row[i*32 + lane];
    float m = -3.4e38f;
    #pragma unroll
    for (int i = 0; i < 16; i++)
        m = fmaxf(m, fmaxf(fmaxf(f[i].x, f[i].y), fmaxf(f[i].z, f[i].w)));
    #pragma unroll
    for (int o = 16; o; o >>= 1) m = fmaxf(m, __shfl_xor_sync(0xffffffffu, m, o));
    float sum = 0.f;
    #pragma unroll
    for (int i = 0; i < 16; i++) {
        f[i].x = __expf(f[i].x - m); f[i].y = __expf(f[i].y - m);
        f[i].z = __expf(f[i].z - m); f[i].w = __expf(f[i].w - m);
        sum += f[i].x + f[i].y + f[i].z + f[i].w;
    }
    #pragma unroll
    for (int o = 16; o; o >>= 1) sum += __shfl_xor_sync(0xffffffffu, sum, o);
    float inv = 1.f / sum;
    #pragma unroll
    for (int i = 0; i < 16; i++) {
        f[i].x *= inv; f[i].y *= inv; f[i].z *= inv; f[i].w *= inv;
        row[i*32 + lane] = f[i];
    }
}

// ====================== PV GEMM (reads normalized fp32 S) ===================
// ctx[bh][m0..+128][64] = P @ V. A double-buffered (split-only conversion),
// V double-buffered via cp.async issued AFTER the barrier (WAR-safe).
// smem: A stages [0,64K) (each 32K: hi 16K + lo 16K), V stages [64K,96K).
__global__ void __launch_bounds__(256) gemm_pv_fused(
    const float* __restrict__ S,
    const __nv_bfloat16* __restrict__ Vhi, const __nv_bfloat16* __restrict__ Vlo,
    __nv_bfloat16* __restrict__ Chi, __nv_bfloat16* __restrict__ Clo)
{
    extern __shared__ char sm[];
    const int tid = threadIdx.x, warp = tid >> 5, lane = tid & 31;
    const int m0 = blockIdx.x * 128;
    const size_t bh = blockIdx.y;
    const int b = (int)(bh >> 4), h = (int)(bh & 15);
    const int wm = (warp & 3) * 32, wn = (warp >> 2) * 32;
    const uint32_t smb = smem_u32(sm);

    float acc[2][4][4];
    #pragma unroll
    for (int i = 0; i < 2; i++)
        #pragma unroll
        for (int j = 0; j < 4; j++)
            #pragma unroll
            for (int q = 0; q < 4; q++) acc[i][j][q] = 0.f;

    // coalesced S-chunk mapping: thread covers rows u*16+(tid>>4), cols (tid&15)*4
    const int frow = tid >> 4, fcol = (tid & 15) * 4;
    const float* Sbase = S + (bh*2048 + (size_t)m0 + frow)*2048 + fcol;
    const int k8 = (tid & 15) >> 1, lo8 = (tid & 1) * 8;

    const int vrow = tid >> 2, vk0 = (tid & 3) * 2;

#define PVF_V(kc, stg) do { \
    uint32_t b_ = smb + 65536 + (stg) * 16384; \
    size_t gv_ = (bh*2048 + (size_t)(kc)*64 + vrow)*64 + vk0*8; \
    _Pragma("unroll") \
    for (int u = 0; u < 2; u++) { \
        uint32_t so = (uint32_t)(vrow*8 + ((vk0 + u) ^ (vrow & 7))) << 4; \
        cpa16(b_ + so,        Vhi + gv_ + u*8); \
        cpa16(b_ + 8192 + so, Vlo + gv_ + u*8); \
    } \
} while (0)

#define PVF_CONV(F, stg) do { \
    char* ab_ = sm + (stg) * 32768; \
    _Pragma("unroll") \
    for (int u = 0; u < 8; u++) { \
        int r_ = u*16 + frow; \
        uint32_t h0, l0, h1, l1; \
        split2((F)[u].x, (F)[u].y, h0, l0); \
        split2((F)[u].z, (F)[u].w, h1, l1); \
        uint32_t so = (uint32_t)(r_*128 + ((k8 ^ (r_ & 7)) << 4) + lo8); \
        *(uint2*)(ab_ + so)         = make_uint2(h0, h1); \
        *(uint2*)(ab_ + 16384 + so) = make_uint2(l0, l1); \
    } \
} while (0)

    // prologue: chunk 0 regs -> A stage 0; V stage 0 in flight
    float4 F[8];
    #pragma unroll
    for (int u = 0; u < 8; u++) F[u] = *(const float4*)(Sbase + (size_t)u*16*2048);
    PVF_CONV(F, 0);
    PVF_V(0, 0); CP_COMMIT();

    for (int kc = 0; kc < 32; kc++) {
        CP_WAIT(0);               // V(kc) landed (only group in flight)
        __syncthreads();          // A(kc) conv-writes visible; all prior-stage reads done
        if (kc + 1 < 32) {
            PVF_V(kc + 1, (kc + 1) & 1); CP_COMMIT();   // WAR-safe: after barrier
            #pragma unroll
            for (int u = 0; u < 8; u++)
                F[u] = *(const float4*)(Sbase + (size_t)u*16*2048 + (kc+1)*64);
        }
        const uint32_t ab = smb + (kc & 1) * 32768;
        const uint32_t vb = smb + 65536 + (kc & 1) * 16384;
        #pragma unroll
        for (int ks = 0; ks < 4; ks++) {
            uint32_t Ah[2][4], Al[2][4], Bh[4][2], Bl[4][2];
            #pragma unroll
            for (int mf = 0; mf < 2; mf++) {
                int r = wm + mf*16 + (lane & 15);
                int ku = ks*2 + (lane >> 4);
                uint32_t ad = ab + ((uint32_t)(r*8 + (ku ^ (r & 7))) << 4);
                ldm_x4(Ah[mf][0], Ah[mf][1], Ah[mf][2], Ah[mf][3], ad);
                ldm_x4(Al[mf][0], Al[mf][1], Al[mf][2], Al[mf][3], ad + 16384);
            }
            #pragma unroll
            for (int nf = 0; nf < 4; nf++) {
                int r = ks*16 + (lane & 15);
                int nu = (wn >> 3) + nf;
                uint32_t bd = vb + ((uint32_t)(r*8 + (nu ^ (r & 7))) << 4);
                ldm_x2t(Bh[nf][0], Bh[nf][1], bd);
                ldm_x2t(Bl[nf][0], Bl[nf][1], bd + 8192);
            }
            #pragma unroll
            for (int mf = 0; mf < 2; mf++)
                #pragma unroll
                for (int nf = 0; nf < 4; nf++) {
                    mma16816(acc[mf][nf], Ah[mf], Bh[nf]);
                    mma16816(acc[mf][nf], Al[mf], Bh[nf]);
                    mma16816(acc[mf][nf], Ah[mf], Bl[nf]);
                }
        }
        // convert next chunk into the other A stage (read at next barrier)
        if (kc + 1 < 32) PVF_CONV(F, (kc + 1) & 1);
    }
#undef PVF_V
#undef PVF_CONV

    #pragma unroll
    for (int mf = 0; mf < 2; mf++)
        #pragma unroll
        for (int nf = 0; nf < 4; nf++) {
            int n = wn + nf*8 + (lane & 3)*2;     // d
            #pragma unroll
            for (int hf = 0; hf < 2; hf++) {
                int m = wm + mf*16 + (lane >> 2) + hf*8;
                size_t o = ((size_t)b*2048 + m0 + m)*1024 + h*64 + n;
                uint32_t H, L;
                split2(acc[mf][nf][hf*2+0], acc[mf][nf][hf*2+1], H, L);
                *(uint32_t*)(Chi + o) = H;
                *(uint32_t*)(Clo + o) = L;
            }
        }
}

// ====================== host ================================================
extern "C" void kernel_launch(void* const* d_in, const int* in_sizes, int n_in,
                              void* d_out, int out_size)
{
    const float* q  = (const float*)d_in[0];
    const float* k  = (const float*)d_in[1];
    const float* v  = (const float*)d_in[2];
    const float* Wq = (const float*)d_in[3];
    const float* bq = (const float*)d_in[4];
    const float* Wk = (const float*)d_in[5];
    const float* bk = (const float*)d_in[6];
    const float* Wv = (const float*)d_in[7];
    const float* bv = (const float*)d_in[8];
    const float* Wo = (const float*)d_in[9];
    const float* bo = (const float*)d_in[10];

    float* outp = (float*)d_out;
    float* final_dst = nullptr;
    float* attn_dst  = nullptr;
    long long osz = (long long)out_size;
    if (osz >= OUTE + ATTNE)      { final_dst = outp; attn_dst = outp + OUTE; }
    else if (osz == ATTNE)        { attn_dst = outp; }
    else                          { final_dst = outp; }

    __nv_bfloat16 *pIhi, *pIlo, *pWhi, *pWlo, *pQhi, *pQlo, *pKhi, *pKlo;
    __nv_bfloat16 *pVhi, *pVlo, *pChi, *pClo;
    float* pS;
    cudaGetSymbolAddress((void**)&pIhi, g_Ihi);
    cudaGetSymbolAddress((void**)&pIlo, g_Ilo);
    cudaGetSymbolAddress((void**)&pWhi, g_Whi);
    cudaGetSymbolAddress((void**)&pWlo, g_Wlo);
    cudaGetSymbolAddress((void**)&pQhi, g_Qhi);
    cudaGetSymbolAddress((void**)&pQlo, g_Qlo);
    cudaGetSymbolAddress((void**)&pKhi, g_Khi);
    cudaGetSymbolAddress((void**)&pKlo, g_Klo);
    cudaGetSymbolAddress((void**)&pVhi, g_Vhi);
    cudaGetSymbolAddress((void**)&pVlo, g_Vlo);
    cudaGetSymbolAddress((void**)&pChi, g_Chi);
    cudaGetSymbolAddress((void**)&pClo, g_Clo);
    cudaGetSymbolAddress((void**)&pS,   g_S);

    float* Sbuf = attn_dst ? attn_dst : pS;

    cudaFuncSetAttribute(gemm_proj_mma,   cudaFuncAttributeMaxDynamicSharedMemorySize, 65536);
    cudaFuncSetAttribute(gemm_scores_mma, cudaFuncAttributeMaxDynamicSharedMemorySize, 65536);
    cudaFuncSetAttribute(gemm_pv_fused,   cudaFuncAttributeMaxDynamicSharedMemorySize, 98304);

    const int n4 = ROWS*DM/4;
    dim3 gr(n4/256, 3);
    split_rm3<<<gr, 256>>>(q, k, v, pIhi, pIlo, n4);
    dim3 gw(32, 32, 4);
    split_w4<<<gw, 256>>>(Wq, Wk, Wv, Wo, pWhi, pWlo);

    dim3 gp(8, 64);
    gemm_proj_mma<<<gp, 256, 65536>>>(pIhi, pIlo, pWhi, pWlo,
                                      bq, 0.125f, 0, nullptr, pQhi, pQlo);
    gemm_proj_mma<<<gp, 256, 65536>>>(pIhi + (size_t)ROWS*DM, pIlo + (size_t)ROWS*DM,
                                      pWhi + (size_t)DM*DM, pWlo + (size_t)DM*DM,
                                      bk, 1.0f, 0, nullptr, pKhi, pKlo);
    gemm_proj_mma<<<gp, 256, 65536>>>(pIhi + 2*(size_t)ROWS*DM, pIlo + 2*(size_t)ROWS*DM,
                                      pWhi + 2*(size_t)DM*DM, pWlo + 2*(size_t)DM*DM,
                                      bv, 1.0f, 0, nullptr, pVhi, pVlo);

    dim3 gs(16, 16, 64);
    gemm_scores_mma<<<gs, 256, 65536>>>(pQhi, pQlo, pKhi, pKlo, Sbuf);
    softmax_k<<<16384, 256>>>(Sbuf);

    if (final_dst) {
        dim3 gv(16, 64);
        gemm_pv_fused<<<gv, 256, 98304>>>(Sbuf, pVhi, pVlo, pChi, pClo);
        gemm_proj_mma<<<gp, 256, 65536>>>(pChi, pClo,
                                          pWhi + 3*(size_t)DM*DM, pWlo + 3*(size_t)DM*DM,
                                          bo, 1.0f, 1, final_dst, nullptr, nullptr);
    }
}

// round 17
// speedup vs baseline: 1.0727x; 1.0714x over previous
#include <cuda_runtime.h>
#include <cuda_bf16.h>
#include <cstdint>

#define BB   4
#define SS   2048
#define DM   1024
#define HH   16
#define DH   64
#define ROWS (BB*SS)          // 8192
#define OUTE  8388608LL
#define ATTNE 268435456LL

// ====================== PTX helpers (sm_80-compatible) ======================
__device__ __forceinline__ uint32_t smem_u32(const void* p) {
    uint32_t a;
    asm("{ .reg .u64 t; cvta.to.shared.u64 t, %1; cvt.u32.u64 %0, t; }"
        : "=r"(a) : "l"(p));
    return a;
}
__device__ __forceinline__ void ldm_x4(uint32_t& r0, uint32_t& r1, uint32_t& r2,
                                       uint32_t& r3, uint32_t a) {
    asm volatile("ldmatrix.sync.aligned.m8n8.x4.shared.b16 {%0,%1,%2,%3}, [%4];"
        : "=r"(r0), "=r"(r1), "=r"(r2), "=r"(r3) : "r"(a));
}
__device__ __forceinline__ void ldm_x2(uint32_t& r0, uint32_t& r1, uint32_t a) {
    asm volatile("ldmatrix.sync.aligned.m8n8.x2.shared.b16 {%0,%1}, [%2];"
        : "=r"(r0), "=r"(r1) : "r"(a));
}
__device__ __forceinline__ void ldm_x2t(uint32_t& r0, uint32_t& r1, uint32_t a) {
    asm volatile("ldmatrix.sync.aligned.m8n8.x2.trans.shared.b16 {%0,%1}, [%2];"
        : "=r"(r0), "=r"(r1) : "r"(a));
}
__device__ __forceinline__ void mma16816(float* c, const uint32_t* a, const uint32_t* b) {
    asm volatile("mma.sync.aligned.m16n8k16.row.col.f32.bf16.bf16.f32 "
        "{%0,%1,%2,%3}, {%4,%5,%6,%7}, {%8,%9}, {%0,%1,%2,%3};"
        : "+f"(c[0]), "+f"(c[1]), "+f"(c[2]), "+f"(c[3])
        : "r"(a[0]), "r"(a[1]), "r"(a[2]), "r"(a[3]), "r"(b[0]), "r"(b[1]));
}
__device__ __forceinline__ void cpa16(uint32_t s, const void* g) {
    asm volatile("cp.async.cg.shared.global [%0], [%1], 16;" :: "r"(s), "l"(g));
}
#define CP_COMMIT() asm volatile("cp.async.commit_group;" ::: "memory")
#define CP_WAIT(n)  asm volatile("cp.async.wait_group %0;" :: "n"(n) : "memory")

__device__ __forceinline__ void split2(float a, float b, uint32_t& hi, uint32_t& lo) {
    __nv_bfloat16 ha = __float2bfloat16(a), hb = __float2bfloat16(b);
    float ra = a - __bfloat162float(ha), rb = b - __bfloat162float(hb);
    __nv_bfloat162 H; H.x = ha; H.y = hb;
    __nv_bfloat162 L; L.x = __float2bfloat16(ra); L.y = __float2bfloat16(rb);
    hi = *reinterpret_cast<uint32_t*>(&H);
    lo = *reinterpret_cast<uint32_t*>(&L);
}

// ====================== device scratch ======================================
__device__ __nv_bfloat16 g_Ihi[3][ROWS*DM], g_Ilo[3][ROWS*DM];
__device__ __nv_bfloat16 g_Whi[4][DM*DM],   g_Wlo[4][DM*DM];   // W^T [n][k]
__device__ __nv_bfloat16 g_Qhi[ROWS*DM], g_Qlo[ROWS*DM];       // [bh][s][64]
__device__ __nv_bfloat16 g_Khi[ROWS*DM], g_Klo[ROWS*DM];
__device__ __nv_bfloat16 g_Vhi[ROWS*DM], g_Vlo[ROWS*DM];       // [bh][s][64]
__device__ __nv_bfloat16 g_Chi[ROWS*DM], g_Clo[ROWS*DM];       // ctx [b][s][1024]
__device__ float g_S[268435456];                               // fallback scores

// ====================== merged split kernels ================================
__global__ void __launch_bounds__(256) split_rm3(
    const float* __restrict__ X0, const float* __restrict__ X1,
    const float* __restrict__ X2, __nv_bfloat16* __restrict__ hi,
    __nv_bfloat16* __restrict__ lo, int n4)
{
    int i = blockIdx.x * 256 + threadIdx.x;
    if (i >= n4) return;
    const float* X = (blockIdx.y == 0) ? X0 : (blockIdx.y == 1) ? X1 : X2;
    size_t off = (size_t)blockIdx.y * (ROWS*DM/4);
    float4 v = ((const float4*)X)[i];
    uint32_t h0, l0, h1, l1;
    split2(v.x, v.y, h0, l0);
    split2(v.z, v.w, h1, l1);
    ((uint2*)hi)[off + i] = make_uint2(h0, h1);
    ((uint2*)lo)[off + i] = make_uint2(l0, l1);
}

// W[K][N] -> T[N][K] hi/lo, 4 weights in one launch (z selects)
__global__ void __launch_bounds__(256) split_w4(
    const float* __restrict__ W0, const float* __restrict__ W1,
    const float* __restrict__ W2, const float* __restrict__ W3,
    __nv_bfloat16* __restrict__ Thi, __nv_bfloat16* __restrict__ Tlo)
{
    __shared__ float ts[32][33];
    const float* W = (blockIdx.z == 0) ? W0 : (blockIdx.z == 1) ? W1
                   : (blockIdx.z == 2) ? W2 : W3;
    size_t zo = (size_t)blockIdx.z * DM * DM;
    int c0 = blockIdx.x * 32, r0 = blockIdx.y * 32;
    int tx = threadIdx.x & 31, ty = threadIdx.x >> 5;
    #pragma unroll
    for (int i = 0; i < 4; i++)
        ts[ty + i*8][tx] = W[(size_t)(r0 + ty + i*8) * DM + c0 + tx];
    __syncthreads();
    #pragma unroll
    for (int i = 0; i < 4; i++) {
        int nn = ty + i*8;
        float x = ts[tx][nn];
        __nv_bfloat16 h = __float2bfloat16(x);
        __nv_bfloat16 l = __float2bfloat16(x - __bfloat162float(h));
        size_t o = zo + (size_t)(c0 + nn) * DM + r0 + tx;
        Thi[o] = h; Tlo[o] = l;
    }
}

// ====================== projection GEMM (BM=128, BN=64, 2 CTA/SM) ===========
// z selects (A slab, W slab, bias, output). mode 0: head bf16 hi/lo; 1: fp32.
// smem/stage 24K: Ahi 8K | Alo 8K | Bhi 4K | Blo 4K. 2 stages = 48K.
__global__ void __launch_bounds__(256, 2) gemm_proj_mma(
    const __nv_bfloat16* __restrict__ Ahi, const __nv_bfloat16* __restrict__ Alo,
    const __nv_bfloat16* __restrict__ Bhi, const __nv_bfloat16* __restrict__ Blo,
    const float* __restrict__ b0, const float* __restrict__ b1,
    const float* __restrict__ b2, float scale0, int mode,
    float* __restrict__ outf, __nv_bfloat16* __restrict__ O0hi,
    __nv_bfloat16* __restrict__ O0lo, __nv_bfloat16* __restrict__ O1hi,
    __nv_bfloat16* __restrict__ O1lo, __nv_bfloat16* __restrict__ O2hi,
    __nv_bfloat16* __restrict__ O2lo)
{
    extern __shared__ char sm[];
    const int tid = threadIdx.x, warp = tid >> 5, lane = tid & 31;
    const int z = blockIdx.z;
    const int m0 = blockIdx.y * 128, nb0 = blockIdx.x * 64;
    const int wm = (warp >> 1) * 32, wn = (warp & 1) * 32;
    const uint32_t smb = smem_u32(sm);

    const __nv_bfloat16* Az_hi = Ahi + (size_t)z * ROWS * DM;
    const __nv_bfloat16* Az_lo = Alo + (size_t)z * ROWS * DM;
    const __nv_bfloat16* Bz_hi = Bhi + (size_t)z * DM * DM;
    const __nv_bfloat16* Bz_lo = Blo + (size_t)z * DM * DM;
    const float* bias = (z == 0) ? b0 : (z == 1) ? b1 : b2;
    const float scale = (z == 0) ? scale0 : 1.0f;
    __nv_bfloat16* Ohi = (z == 0) ? O0hi : (z == 1) ? O1hi : O2hi;
    __nv_bfloat16* Olo = (z == 0) ? O0lo : (z == 1) ? O1lo : O2lo;

    float acc[2][4][4];
    #pragma unroll
    for (int i = 0; i < 2; i++)
        #pragma unroll
        for (int j = 0; j < 4; j++)
            #pragma unroll
            for (int q = 0; q < 4; q++) acc[i][j][q] = 0.f;

    const int lrow = tid >> 1, lk0 = (tid & 1) * 2;        // A: 2 units/thread
    const int brow = tid >> 2, bc4 = tid & 3;              // B: 1 unit/thread
    const size_t gA = (size_t)(m0 + lrow) * DM + lk0 * 8;
    const size_t gB = (size_t)(nb0 + brow) * DM + bc4 * 8;
    const uint32_t sA0 = (uint32_t)(lrow*4 + ((lk0)   ^ (lrow & 3))) << 4;
    const uint32_t sA1 = (uint32_t)(lrow*4 + ((lk0+1) ^ (lrow & 3))) << 4;
    const uint32_t sB  = (uint32_t)(brow*4 + (bc4 ^ (brow & 3))) << 4;

#define PJ_PREFETCH(kc, st) do { \
    uint32_t b_ = smb + (st) * 24576; \
    const __nv_bfloat16* a0_ = Az_hi + gA + (kc)*32; \
    const __nv_bfloat16* a1_ = Az_lo + gA + (kc)*32; \
    cpa16(b_ + sA0, a0_);          cpa16(b_ + sA1, a0_ + 8); \
    cpa16(b_ + 8192 + sA0, a1_);   cpa16(b_ + 8192 + sA1, a1_ + 8); \
    cpa16(b_ + 16384 + sB, Bz_hi + gB + (kc)*32); \
    cpa16(b_ + 20480 + sB, Bz_lo + gB + (kc)*32); \
} while (0)

    PJ_PREFETCH(0, 0); CP_COMMIT();
    for (int kc = 0; kc < 32; kc++) {
        if (kc + 1 < 32) { PJ_PREFETCH(kc + 1, (kc + 1) & 1); CP_COMMIT(); CP_WAIT(1); }
        else CP_WAIT(0);
        __syncthreads();
        const uint32_t ab = smb + (kc & 1) * 24576;
        #pragma unroll
        for (int ks = 0; ks < 2; ks++) {
            uint32_t Ah[2][4], Al[2][4], Bh[4][2], Bl[4][2];
            #pragma unroll
            for (int mf = 0; mf < 2; mf++) {
                int r = wm + mf*16 + (lane & 15);
                int ku = ks*2 + (lane >> 4);
                uint32_t ad = ab + ((uint32_t)(r*4 + (ku ^ (r & 3))) << 4);
                ldm_x4(Ah[mf][0], Ah[mf][1], Ah[mf][2], Ah[mf][3], ad);
                ldm_x4(Al[mf][0], Al[mf][1], Al[mf][2], Al[mf][3], ad + 8192);
            }
            #pragma unroll
            for (int nf = 0; nf < 4; nf++) {
                int r = wn + nf*8 + (lane & 7);
                int ku = ks*2 + ((lane >> 3) & 1);
                uint32_t bd = ab + 16384 + ((uint32_t)(r*4 + (ku ^ (r & 3))) << 4);
                ldm_x2(Bh[nf][0], Bh[nf][1], bd);
                ldm_x2(Bl[nf][0], Bl[nf][1], bd + 4096);
            }
            #pragma unroll
            for (int mf = 0; mf < 2; mf++)
                #pragma unroll
                for (int nf = 0; nf < 4; nf++) {
                    mma16816(acc[mf][nf], Ah[mf], Bh[nf]);
                    mma16816(acc[mf][nf], Al[mf], Bh[nf]);
                    mma16816(acc[mf][nf], Ah[mf], Bl[nf]);
                }
        }
        __syncthreads();
    }
#undef PJ_PREFETCH

    #pragma unroll
    for (int mf = 0; mf < 2; mf++)
        #pragma unroll
        for (int nf = 0; nf < 4; nf++) {
            int d = wn + nf*8 + (lane & 3)*2;          // 0..63
            float bv0 = bias[nb0 + d], bv1 = bias[nb0 + d + 1];
            #pragma unroll
            for (int hf = 0; hf < 2; hf++) {
                int row = m0 + wm + mf*16 + (lane >> 2) + hf*8;
                float v0 = (acc[mf][nf][hf*2+0] + bv0) * scale;
                float v1 = (acc[mf][nf][hf*2+1] + bv1) * scale;
                if (mode == 0) {
                    int b = row >> 11, s = row & 2047, h = nb0 >> 6;
                    size_t o = (((size_t)(b*16 + h))*2048 + s)*64 + d;
                    uint32_t H, L; split2(v0, v1, H, L);
                    *(uint32_t*)(Ohi + o) = H;
                    *(uint32_t*)(Olo + o) = L;
                } else {
                    *(float2*)(outf + (size_t)row*DM + nb0 + d) = make_float2(v0, v1);
                }
            }
        }
}

// ====================== scores GEMM (BM=128, BN=64, one-shot K=64) ==========
// smem: Qhi 16K | Qlo 16K | Khi 8K | Klo 8K = 48K
__global__ void __launch_bounds__(256, 2) gemm_scores_mma(
    const __nv_bfloat16* __restrict__ Qhi, const __nv_bfloat16* __restrict__ Qlo,
    const __nv_bfloat16* __restrict__ Khi, const __nv_bfloat16* __restrict__ Klo,
    float* __restrict__ S)
{
    extern __shared__ char sm[];
    const int tid = threadIdx.x, warp = tid >> 5, lane = tid & 31;
    const int n0 = blockIdx.x * 64, m0 = blockIdx.y * 128;
    const size_t bh = blockIdx.z;
    const int wm = (warp >> 1) * 32, wn = (warp & 1) * 32;
    const uint32_t smb = smem_u32(sm);

    {
        const int lrow = tid >> 1, lk0 = (tid & 1) * 4;
        const __nv_bfloat16* Qh = Qhi + (bh*2048 + m0 + lrow)*64 + lk0*8;
        const __nv_bfloat16* Ql = Qlo + (bh*2048 + m0 + lrow)*64 + lk0*8;
        #pragma unroll
        for (int u = 0; u < 4; u++) {
            uint32_t so = (uint32_t)(lrow*8 + ((lk0 + u) ^ (lrow & 7))) << 4;
            cpa16(smb + so,          Qh + u*8);
            cpa16(smb + 16384 + so,  Ql + u*8);
        }
        const int krow = tid >> 2, kc0 = (tid & 3) * 2;
        const __nv_bfloat16* Kh = Khi + (bh*2048 + n0 + krow)*64 + kc0*8;
        const __nv_bfloat16* Kl = Klo + (bh*2048 + n0 + krow)*64 + kc0*8;
        #pragma unroll
        for (int u = 0; u < 2; u++) {
            uint32_t so = (uint32_t)(krow*8 + ((kc0 + u) ^ (krow & 7))) << 4;
            cpa16(smb + 32768 + so, Kh + u*8);
            cpa16(smb + 40960 + so, Kl + u*8);
        }
    }
    CP_COMMIT(); CP_WAIT(0);
    __syncthreads();

    float acc[2][4][4];
    #pragma unroll
    for (int i = 0; i < 2; i++)
        #pragma unroll
        for (int j = 0; j < 4; j++)
            #pragma unroll
            for (int q = 0; q < 4; q++) acc[i][j][q] = 0.f;

    #pragma unroll
    for (int ks = 0; ks < 4; ks++) {
        uint32_t Ah[2][4], Al[2][4], Bh[4][2], Bl[4][2];
        #pragma unroll
        for (int mf = 0; mf < 2; mf++) {
            int r = wm + mf*16 + (lane & 15);
            int ku = ks*2 + (lane >> 4);
            uint32_t ad = smb + ((uint32_t)(r*8 + (ku ^ (r & 7))) << 4);
            ldm_x4(Ah[mf][0], Ah[mf][1], Ah[mf][2], Ah[mf][3], ad);
            ldm_x4(Al[mf][0], Al[mf][1], Al[mf][2], Al[mf][3], ad + 16384);
        }
        #pragma unroll
        for (int nf = 0; nf < 4; nf++) {
            int r = wn + nf*8 + (lane & 7);
            int ku = ks*2 + ((lane >> 3) & 1);
            uint32_t bd = smb + 32768 + ((uint32_t)(r*8 + (ku ^ (r & 7))) << 4);
            ldm_x2(Bh[nf][0], Bh[nf][1], bd);
            ldm_x2(Bl[nf][0], Bl[nf][1], bd + 8192);
        }
        #pragma unroll
        for (int mf = 0; mf < 2; mf++)
            #pragma unroll
            for (int nf = 0; nf < 4; nf++) {
                mma16816(acc[mf][nf], Ah[mf], Bh[nf]);
                mma16816(acc[mf][nf], Al[mf], Bh[nf]);
                mma16816(acc[mf][nf], Ah[mf], Bl[nf]);
            }
    }

    float* Sb = S + (bh*2048 + (size_t)m0)*2048 + n0;
    #pragma unroll
    for (int mf = 0; mf < 2; mf++)
        #pragma unroll
        for (int nf = 0; nf < 4; nf++) {
            int n = wn + nf*8 + (lane & 3)*2;
            #pragma unroll
            for (int hf = 0; hf < 2; hf++) {
                int m = wm + mf*16 + (lane >> 2) + hf*8;
                *(float2*)(Sb + (size_t)m*2048 + n) =
                    make_float2(acc[mf][nf][hf*2+0], acc[mf][nf][hf*2+1]);
            }
        }
}

// ====================== softmax (in place, warp per row) ====================
__global__ void __launch_bounds__(256) softmax_k(float* __restrict__ S)
{
    size_t rowi = (size_t)blockIdx.x * 8 + (threadIdx.x >> 5);
    int lane = threadIdx.x & 31;
    float4* row = (float4*)(S + rowi * 2048);
    float4 f[16];
    #pragma unroll
    for (int i = 0; i < 16; i++) f[i] = row[i*32 + lane];
    float m = -3.4e38f;
    #pragma unroll
    for (int i = 0; i < 16; i++)
        m = fmaxf(m, fmaxf(fmaxf(f[i].x, f[i].y), fmaxf(f[i].z, f[i].w)));
    #pragma unroll
    for (int o = 16; o; o >>= 1) m = fmaxf(m, __shfl_xor_sync(0xffffffffu, m, o));
    float sum = 0.f;
    #pragma unroll
    for (int i = 0; i < 16; i++) {
        f[i].x = __expf(f[i].x - m); f[i].y = __expf(f[i].y - m);
        f[i].z = __expf(f[i].z - m); f[i].w = __expf(f[i].w - m);
        sum += f[i].x + f[i].y + f[i].z + f[i].w;
    }
    #pragma unroll
    for (int o = 16; o; o >>= 1) sum += __shfl_xor_sync(0xffffffffu, sum, o);
    float inv = 1.f / sum;
    #pragma unroll
    for (int i = 0; i < 16; i++) {
        f[i].x *= inv; f[i].y *= inv; f[i].z *= inv; f[i].w *= inv;
        row[i*32 + lane] = f[i];
    }
}

// ====================== PV GEMM (reads normalized fp32 S) ===================
__global__ void __launch_bounds__(256) gemm_pv_fused(
    const float* __restrict__ S,
    const __nv_bfloat16* __restrict__ Vhi, const __nv_bfloat16* __restrict__ Vlo,
    __nv_bfloat16* __restrict__ Chi, __nv_bfloat16* __restrict__ Clo)
{
    extern __shared__ char sm[];
    const int tid = threadIdx.x, warp = tid >> 5, lane = tid & 31;
    const int m0 = blockIdx.x * 128;
    const size_t bh = blockIdx.y;
    const int b = (int)(bh >> 4), h = (int)(bh & 15);
    const int wm = (warp & 3) * 32, wn = (warp >> 2) * 32;
    const uint32_t smb = smem_u32(sm);

    float acc[2][4][4];
    #pragma unroll
    for (int i = 0; i < 2; i++)
        #pragma unroll
        for (int j = 0; j < 4; j++)
            #pragma unroll
            for (int q = 0; q < 4; q++) acc[i][j][q] = 0.f;

    const int frow = tid >> 4, fcol = (tid & 15) * 4;
    const float* Sbase = S + (bh*2048 + (size_t)m0 + frow)*2048 + fcol;
    const int k8 = (tid & 15) >> 1, lo8 = (tid & 1) * 8;

    const int vrow = tid >> 2, vk0 = (tid & 3) * 2;

#define PVF_V(kc, stg) do { \
    uint32_t b_ = smb + 65536 + (stg) * 16384; \
    size_t gv_ = (bh*2048 + (size_t)(kc)*64 + vrow)*64 + vk0*8; \
    _Pragma("unroll") \
    for (int u = 0; u < 2; u++) { \
        uint32_t so = (uint32_t)(vrow*8 + ((vk0 + u) ^ (vrow & 7))) << 4; \
        cpa16(b_ + so,        Vhi + gv_ + u*8); \
        cpa16(b_ + 8192 + so, Vlo + gv_ + u*8); \
    } \
} while (0)

#define PVF_CONV(F, stg) do { \
    char* ab_ = sm + (stg) * 32768; \
    _Pragma("unroll") \
    for (int u = 0; u < 8; u++) { \
        int r_ = u*16 + frow; \
        uint32_t h0, l0, h1, l1; \
        split2((F)[u].x, (F)[u].y, h0, l0); \
        split2((F)[u].z, (F)[u].w, h1, l1); \
        uint32_t so = (uint32_t)(r_*128 + ((k8 ^ (r_ & 7)) << 4) + lo8); \
        *(uint2*)(ab_ + so)         = make_uint2(h0, h1); \
        *(uint2*)(ab_ + 16384 + so) = make_uint2(l0, l1); \
    } \
} while (0)

    float4 F[8];
    #pragma unroll
    for (int u = 0; u < 8; u++) F[u] = *(const float4*)(Sbase + (size_t)u*16*2048);
    PVF_CONV(F, 0);
    PVF_V(0, 0); CP_COMMIT();

    for (int kc = 0; kc < 32; kc++) {
        CP_WAIT(0);
        __syncthreads();
        if (kc + 1 < 32) {
            PVF_V(kc + 1, (kc + 1) & 1); CP_COMMIT();
            #pragma unroll
            for (int u = 0; u < 8; u++)
                F[u] = *(const float4*)(Sbase + (size_t)u*16*2048 + (kc+1)*64);
        }
        const uint32_t ab = smb + (kc & 1) * 32768;
        const uint32_t vb = smb + 65536 + (kc & 1) * 16384;
        #pragma unroll
        for (int ks = 0; ks < 4; ks++) {
            uint32_t Ah[2][4], Al[2][4], Bh[4][2], Bl[4][2];
            #pragma unroll
            for (int mf = 0; mf < 2; mf++) {
                int r = wm + mf*16 + (lane & 15);
                int ku = ks*2 + (lane >> 4);
                uint32_t ad = ab + ((uint32_t)(r*8 + (ku ^ (r & 7))) << 4);
                ldm_x4(Ah[mf][0], Ah[mf][1], Ah[mf][2], Ah[mf][3], ad);
                ldm_x4(Al[mf][0], Al[mf][1], Al[mf][2], Al[mf][3], ad + 16384);
            }
            #pragma unroll
            for (int nf = 0; nf < 4; nf++) {
                int r = ks*16 + (lane & 15);
                int nu = (wn >> 3) + nf;
                uint32_t bd = vb + ((uint32_t)(r*8 + (nu ^ (r & 7))) << 4);
                ldm_x2t(Bh[nf][0], Bh[nf][1], bd);
                ldm_x2t(Bl[nf][0], Bl[nf][1], bd + 8192);
            }
            #pragma unroll
            for (int mf = 0; mf < 2; mf++)
                #pragma unroll
                for (int nf = 0; nf < 4; nf++) {
                    mma16816(acc[mf][nf], Ah[mf], Bh[nf]);
                    mma16816(acc[mf][nf], Al[mf], Bh[nf]);
                    mma16816(acc[mf][nf], Ah[mf], Bl[nf]);
                }
        }
        if (kc + 1 < 32) PVF_CONV(F, (kc + 1) & 1);
    }
#undef PVF_V
#undef PVF_CONV

    #pragma unroll
    for (int mf = 0; mf < 2; mf++)
        #pragma unroll
        for (int nf = 0; nf < 4; nf++) {
            int n = wn + nf*8 + (lane & 3)*2;
            #pragma unroll
            for (int hf = 0; hf < 2; hf++) {
                int m = wm + mf*16 + (lane >> 2) + hf*8;
                size_t o = ((size_t)b*2048 + m0 + m)*1024 + h*64 + n;
                uint32_t H, L;
                split2(acc[mf][nf][hf*2+0], acc[mf][nf][hf*2+1], H, L);
                *(uint32_t*)(Chi + o) = H;
                *(uint32_t*)(Clo + o) = L;
            }
        }
}

// ====================== host ================================================
extern "C" void kernel_launch(void* const* d_in, const int* in_sizes, int n_in,
                              void* d_out, int out_size)
{
    const float* q  = (const float*)d_in[0];
    const float* k  = (const float*)d_in[1];
    const float* v  = (const float*)d_in[2];
    const float* Wq = (const float*)d_in[3];
    const float* bq = (const float*)d_in[4];
    const float* Wk = (const float*)d_in[5];
    const float* bk = (const float*)d_in[6];
    const float* Wv = (const float*)d_in[7];
    const float* bv = (const float*)d_in[8];
    const float* Wo = (const float*)d_in[9];
    const float* bo = (const float*)d_in[10];

    float* outp = (float*)d_out;
    float* final_dst = nullptr;
    float* attn_dst  = nullptr;
    long long osz = (long long)out_size;
    if (osz >= OUTE + ATTNE)      { final_dst = outp; attn_dst = outp + OUTE; }
    else if (osz == ATTNE)        { attn_dst = outp; }
    else                          { final_dst = outp; }

    __nv_bfloat16 *pIhi, *pIlo, *pWhi, *pWlo, *pQhi, *pQlo, *pKhi, *pKlo;
    __nv_bfloat16 *pVhi, *pVlo, *pChi, *pClo;
    float* pS;
    cudaGetSymbolAddress((void**)&pIhi, g_Ihi);
    cudaGetSymbolAddress((void**)&pIlo, g_Ilo);
    cudaGetSymbolAddress((void**)&pWhi, g_Whi);
    cudaGetSymbolAddress((void**)&pWlo, g_Wlo);
    cudaGetSymbolAddress((void**)&pQhi, g_Qhi);
    cudaGetSymbolAddress((void**)&pQlo, g_Qlo);
    cudaGetSymbolAddress((void**)&pKhi, g_Khi);
    cudaGetSymbolAddress((void**)&pKlo, g_Klo);
    cudaGetSymbolAddress((void**)&pVhi, g_Vhi);
    cudaGetSymbolAddress((void**)&pVlo, g_Vlo);
    cudaGetSymbolAddress((void**)&pChi, g_Chi);
    cudaGetSymbolAddress((void**)&pClo, g_Clo);
    cudaGetSymbolAddress((void**)&pS,   g_S);

    float* Sbuf = attn_dst ? attn_dst : pS;

    cudaFuncSetAttribute(gemm_proj_mma,   cudaFuncAttributeMaxDynamicSharedMemorySize, 49152);
    cudaFuncSetAttribute(gemm_scores_mma, cudaFuncAttributeMaxDynamicSharedMemorySize, 49152);
    cudaFuncSetAttribute(gemm_pv_fused,   cudaFuncAttributeMaxDynamicSharedMemorySize, 98304);

    const int n4 = ROWS*DM/4;
    dim3 gr(n4/256, 3);
    split_rm3<<<gr, 256>>>(q, k, v, pIhi, pIlo, n4);
    dim3 gw(32, 32, 4);
    split_w4<<<gw, 256>>>(Wq, Wk, Wv, Wo, pWhi, pWlo);

    // merged QKV projections: grid (DM/64, ROWS/128, 3)
    dim3 gp(16, 64, 3);
    gemm_proj_mma<<<gp, 256, 49152>>>(pIhi, pIlo, pWhi, pWlo,
                                      bq, bk, bv, 0.125f, 0, nullptr,
                                      pQhi, pQlo, pKhi, pKlo, pVhi, pVlo);

    dim3 gs(32, 16, 64);
    gemm_scores_mma<<<gs, 256, 49152>>>(pQhi, pQlo, pKhi, pKlo, Sbuf);
    softmax_k<<<16384, 256>>>(Sbuf);

    if (final_dst) {
        dim3 gv(16, 64);
        gemm_pv_fused<<<gv, 256, 98304>>>(Sbuf, pVhi, pVlo, pChi, pClo);
        dim3 go(16, 64, 1);
        gemm_proj_mma<<<go, 256, 49152>>>(pChi, pClo,
                                          pWhi + 3*(size_t)DM*DM, pWlo + 3*(size_t)DM*DM,
                                          bo, bo, bo, 1.0f, 1, final_dst,
                                          nullptr, nullptr, nullptr, nullptr,
                                          nullptr, nullptr);
    }
}